// round 1
// baseline (speedup 1.0000x reference)
#include <cuda_runtime.h>
#include <math.h>

#define T_STEPS 16384
#define IDIM 1024
#define HDIM 1024
#define GDIM 4096
#define NBLK 128
#define RTHREADS 256

// ---------------- device globals (scratch; no allocations allowed) ------------
__device__ float g_xgates[(size_t)T_STEPS * GDIM];        // 256 MB precomputed input gates
__device__ __align__(16) float g_h[2][HDIM];              // double-buffered hidden state
__device__ unsigned g_bar;                                // monotonic barrier counter

// ---------------- packed f32x2 helpers ---------------------------------------
static __device__ __forceinline__ unsigned long long pk2(float lo, float hi) {
    unsigned long long r;
    asm("mov.b64 %0, {%1, %2};" : "=l"(r) : "f"(lo), "f"(hi));
    return r;
}
static __device__ __forceinline__ void fma2(unsigned long long& d,
                                            unsigned long long a,
                                            unsigned long long b) {
    asm("fma.rn.f32x2 %0, %1, %2, %0;" : "+l"(d) : "l"(a), "l"(b));
}
static __device__ __forceinline__ float2 up2(unsigned long long v) {
    float2 f;
    asm("mov.b64 {%0, %1}, %2;" : "=f"(f.x), "=f"(f.y) : "l"(v));
    return f;
}

// ---------------- init: reset barrier each launch -----------------------------
__global__ void init_kernel() { g_bar = 0u; }

// ---------------- GEMM: x_gates = A @ W_ih^T + (b_ih + b_hh) ------------------
// A [T, I] row-major, W [G, I] row-major (both K-major -> "NT" GEMM).
// Block tile 128x128, K-tile 8, 256 threads, 8x8 microtile, packed f32x2 FMAs.
__global__ __launch_bounds__(256) void gemm_kernel(
    const float* __restrict__ A, const float* __restrict__ W,
    const float* __restrict__ bih, const float* __restrict__ bhh) {
    __shared__ float As[8][132];
    __shared__ float Bs[8][132];

    const int tid = threadIdx.x;
    const int m0 = blockIdx.x * 128;
    const int n0 = blockIdx.y * 128;
    const int lrow = tid >> 1;          // 0..127
    const int kq = (tid & 1) * 4;       // 0 or 4
    const int tm = (tid & 15) * 8;      // micro-tile row base
    const int tn = (tid >> 4) * 8;      // micro-tile col base

    unsigned long long acc[4][8];
#pragma unroll
    for (int i = 0; i < 4; i++)
#pragma unroll
        for (int j = 0; j < 8; j++) acc[i][j] = 0ULL;

    const float* aptr = A + (size_t)(m0 + lrow) * IDIM + kq;
    const float* wptr = W + (size_t)(n0 + lrow) * IDIM + kq;

    float4 av = *(const float4*)aptr;
    float4 bv = *(const float4*)wptr;

    for (int k0 = 0; k0 < IDIM; k0 += 8) {
        __syncthreads();
        As[kq + 0][lrow] = av.x; As[kq + 1][lrow] = av.y;
        As[kq + 2][lrow] = av.z; As[kq + 3][lrow] = av.w;
        Bs[kq + 0][lrow] = bv.x; Bs[kq + 1][lrow] = bv.y;
        Bs[kq + 2][lrow] = bv.z; Bs[kq + 3][lrow] = bv.w;
        __syncthreads();
        if (k0 + 8 < IDIM) {            // prefetch next K-tile
            av = *(const float4*)(aptr + k0 + 8);
            bv = *(const float4*)(wptr + k0 + 8);
        }
#pragma unroll
        for (int k = 0; k < 8; k++) {
            float4 a0 = *(const float4*)&As[k][tm];
            float4 a1 = *(const float4*)&As[k][tm + 4];
            float4 b0 = *(const float4*)&Bs[k][tn];
            float4 b1 = *(const float4*)&Bs[k][tn + 4];
            unsigned long long am[4] = { pk2(a0.x, a0.y), pk2(a0.z, a0.w),
                                         pk2(a1.x, a1.y), pk2(a1.z, a1.w) };
            float bb[8] = { b0.x, b0.y, b0.z, b0.w, b1.x, b1.y, b1.z, b1.w };
#pragma unroll
            for (int j = 0; j < 8; j++) {
                unsigned long long b2 = pk2(bb[j], bb[j]);
                fma2(acc[0][j], am[0], b2);
                fma2(acc[1][j], am[1], b2);
                fma2(acc[2][j], am[2], b2);
                fma2(acc[3][j], am[3], b2);
            }
        }
    }

    float bias[8];
#pragma unroll
    for (int j = 0; j < 8; j++) bias[j] = bih[n0 + tn + j] + bhh[n0 + tn + j];

#pragma unroll
    for (int i = 0; i < 4; i++) {
        float r0v[8], r1v[8];
#pragma unroll
        for (int j = 0; j < 8; j++) {
            float2 p = up2(acc[i][j]);
            r0v[j] = p.x + bias[j];
            r1v[j] = p.y + bias[j];
        }
        size_t row0 = (size_t)(m0 + tm + 2 * i) * GDIM + n0 + tn;
        size_t row1 = row0 + GDIM;
        *(float4*)&g_xgates[row0]     = make_float4(r0v[0], r0v[1], r0v[2], r0v[3]);
        *(float4*)&g_xgates[row0 + 4] = make_float4(r0v[4], r0v[5], r0v[6], r0v[7]);
        *(float4*)&g_xgates[row1]     = make_float4(r1v[0], r1v[1], r1v[2], r1v[3]);
        *(float4*)&g_xgates[row1 + 4] = make_float4(r1v[4], r1v[5], r1v[6], r1v[7]);
    }
}

// ---------------- persistent LSTM recurrence ----------------------------------
// 128 CTAs x 256 threads, all co-resident (<=148 SMs). CTA b owns h elements
// [8b, 8b+8) => 32 gate rows (4 gates x 8 elems). W_hh slice lives in REGISTERS:
// thread (warp w, lane cg) holds rows {4w..4w+3} x cols {cg + 32*c0 : c0<32}
// as 64 packed f32x2 values. Per step: spin-barrier -> load h -> 64 f32x2 FMAs
// -> full-warp shfl reduce -> activations on threads 0..7 (c in registers).
__global__ __launch_bounds__(RTHREADS) void lstm_kernel(const float* __restrict__ Whh) {
    __shared__ __align__(16) float sh_h[HDIM];
    __shared__ float sh_g[32];

    const int tid = threadIdx.x;
    const int w = tid >> 5;             // warp 0..7
    const int cg = tid & 31;            // lane
    const int b = blockIdx.x;           // 0..127
    const int gate = w >> 1;            // 0..3
    const int ebase = (w & 1) * 4;      // 0 or 4
    const int r0 = gate * HDIM + b * 8 + ebase;   // 4 consecutive global rows

    // Load W_hh slice into registers (coalesced: lanes read consecutive cols).
    unsigned long long w0[32], w1[32];
#pragma unroll
    for (int c0 = 0; c0 < 32; c0++) {
        int col = cg + 32 * c0;
        w0[c0] = pk2(Whh[(size_t)(r0 + 0) * HDIM + col],
                     Whh[(size_t)(r0 + 1) * HDIM + col]);
        w1[c0] = pk2(Whh[(size_t)(r0 + 2) * HDIM + col],
                     Whh[(size_t)(r0 + 3) * HDIM + col]);
    }

    float c_state = 0.0f;   // valid for tid < 8 (element e = tid)

    for (int t = 0; t < T_STEPS; t++) {
        // Prefetch this step's xg row chunk (independent of h -> hides latency
        // behind the barrier wait).
        float4 xg;
        if (cg == 0)
            xg = *(const float4*)&g_xgates[(size_t)t * GDIM + r0];

        if (t > 0) {
            if (tid == 0) {
                const unsigned target = (unsigned)t * (unsigned)NBLK;
                unsigned v;
                do {
                    asm volatile("ld.acquire.gpu.u32 %0, [%1];"
                                 : "=r"(v) : "l"(&g_bar) : "memory");
                } while (v < target);
            }
            __syncthreads();
            // h from peers: bypass L1 (other SMs wrote it).
            const float4* hb = (const float4*)g_h[t & 1];
            ((float4*)sh_h)[tid] = __ldcg(&hb[tid]);
        } else {
            ((float4*)sh_h)[tid] = make_float4(0.f, 0.f, 0.f, 0.f);
        }
        __syncthreads();

        unsigned long long acc0 = 0ULL, acc1 = 0ULL;
#pragma unroll
        for (int c0 = 0; c0 < 32; c0++) {
            float hv = sh_h[cg + 32 * c0];      // conflict-free (bank = cg)
            unsigned long long hh = pk2(hv, hv);
            fma2(acc0, w0[c0], hh);
            fma2(acc1, w1[c0], hh);
        }

        float2 a0 = up2(acc0), a1 = up2(acc1);
#pragma unroll
        for (int off = 16; off; off >>= 1) {
            a0.x += __shfl_xor_sync(0xffffffffu, a0.x, off);
            a0.y += __shfl_xor_sync(0xffffffffu, a0.y, off);
            a1.x += __shfl_xor_sync(0xffffffffu, a1.x, off);
            a1.y += __shfl_xor_sync(0xffffffffu, a1.y, off);
        }
        if (cg == 0) {
            sh_g[w * 4 + 0] = a0.x + xg.x;
            sh_g[w * 4 + 1] = a0.y + xg.y;
            sh_g[w * 4 + 2] = a1.x + xg.z;
            sh_g[w * 4 + 3] = a1.y + xg.w;
        }
        __syncthreads();

        if (tid < 8) {
            float gi = sh_g[tid];
            float gf = sh_g[8 + tid];
            float gg = sh_g[16 + tid];
            float go = sh_g[24 + tid];
            float i_ = 1.0f / (1.0f + __expf(-gi));
            float f_ = 1.0f / (1.0f + __expf(-gf));
            float g_ = tanhf(gg);
            float o_ = 1.0f / (1.0f + __expf(-go));
            c_state = f_ * c_state + i_ * g_;
            float hn = o_ * tanhf(c_state);
            g_h[(t + 1) & 1][b * 8 + tid] = hn;
        }
        __syncthreads();

        if (tid == 0) {
            asm volatile("red.release.gpu.add.u32 [%0], %1;"
                         :: "l"(&g_bar), "r"(1u) : "memory");
        }
    }
}

// ---------------- final: out = W_lin @ h_last + b_lin -------------------------
__global__ void final_kernel(const float* __restrict__ Wl,
                             const float* __restrict__ bl,
                             float* __restrict__ out) {
    __shared__ float partial[32];
    const int tid = threadIdx.x;     // 1024 threads
    float v = Wl[tid] * g_h[0][tid]; // h after T=16384 steps lives in buffer 0
#pragma unroll
    for (int off = 16; off; off >>= 1) v += __shfl_xor_sync(0xffffffffu, v, off);
    if ((tid & 31) == 0) partial[tid >> 5] = v;
    __syncthreads();
    if (tid < 32) {
        float s = partial[tid];
#pragma unroll
        for (int off = 16; off; off >>= 1) s += __shfl_xor_sync(0xffffffffu, s, off);
        if (tid == 0) out[0] = s + bl[0];
    }
}

// ---------------- launch -------------------------------------------------------
extern "C" void kernel_launch(void* const* d_in, const int* in_sizes, int n_in,
                              void* d_out, int out_size) {
    const float* input = (const float*)d_in[0];   // [T, I]
    const float* W_ih  = (const float*)d_in[1];   // [4H, I]
    const float* W_hh  = (const float*)d_in[2];   // [4H, H]
    const float* b_ih  = (const float*)d_in[3];   // [4H]
    const float* b_hh  = (const float*)d_in[4];   // [4H]
    const float* W_lin = (const float*)d_in[5];   // [1, H]
    const float* b_lin = (const float*)d_in[6];   // [1]
    float* out = (float*)d_out;

    init_kernel<<<1, 1>>>();

    dim3 ggrid(T_STEPS / 128, GDIM / 128);        // (128, 32)
    gemm_kernel<<<ggrid, 256>>>(input, W_ih, b_ih, b_hh);

    lstm_kernel<<<NBLK, RTHREADS>>>(W_hh);

    final_kernel<<<1, 1024>>>(W_lin, b_lin, out);
}

// round 5
// speedup vs baseline: 1.0567x; 1.0567x over previous
#include <cuda_runtime.h>
#include <math.h>

#define T_STEPS 16384
#define IDIM 1024
#define HDIM 1024
#define GDIM 4096
#define NBLK 128
#define RTHREADS 256
#define NGRP 8            // barrier counter shards
#define CTAS_PER_GRP (NBLK / NGRP)   // 16

// ---------------- device globals (scratch; no allocations allowed) ------------
__device__ float g_xgates[(size_t)T_STEPS * GDIM];   // 256 MB input gates
__device__ __align__(16) float g_h[2][HDIM];         // double-buffered hidden state
__device__ unsigned g_ctr[NGRP * 32];                // 8 counters, 128B apart

// ---------------- packed f32x2 helpers ---------------------------------------
static __device__ __forceinline__ unsigned long long pk2(float lo, float hi) {
    unsigned long long r;
    asm("mov.b64 %0, {%1, %2};" : "=l"(r) : "f"(lo), "f"(hi));
    return r;
}
static __device__ __forceinline__ void fma2(unsigned long long& d,
                                            unsigned long long a,
                                            unsigned long long b) {
    asm("fma.rn.f32x2 %0, %1, %2, %0;" : "+l"(d) : "l"(a), "l"(b));
}
static __device__ __forceinline__ float2 up2(unsigned long long v) {
    float2 f;
    asm("mov.b64 {%0, %1}, %2;" : "=f"(f.x), "=f"(f.y) : "l"(v));
    return f;
}
static __device__ __forceinline__ float fast_sigmoid(float x) {
    return __fdividef(1.0f, 1.0f + __expf(-x));
}
static __device__ __forceinline__ float fast_tanh(float x) {
    return 1.0f - __fdividef(2.0f, __expf(2.0f * x) + 1.0f);
}

// ---------------- init: reset counters each launch (graph replays!) -----------
__global__ void init_kernel() {
    int i = threadIdx.x;
    if (i < NGRP * 32) g_ctr[i] = 0u;
}

// ---------------- GEMM: x_gates = A @ W_ih^T + (b_ih + b_hh) ------------------
// (unchanged from the R1-passing version)
__global__ __launch_bounds__(256) void gemm_kernel(
    const float* __restrict__ A, const float* __restrict__ W,
    const float* __restrict__ bih, const float* __restrict__ bhh) {
    __shared__ float As[8][132];
    __shared__ float Bs[8][132];

    const int tid = threadIdx.x;
    const int m0 = blockIdx.x * 128;
    const int n0 = blockIdx.y * 128;
    const int lrow = tid >> 1;
    const int kq = (tid & 1) * 4;
    const int tm = (tid & 15) * 8;
    const int tn = (tid >> 4) * 8;

    unsigned long long acc[4][8];
#pragma unroll
    for (int i = 0; i < 4; i++)
#pragma unroll
        for (int j = 0; j < 8; j++) acc[i][j] = 0ULL;

    const float* aptr = A + (size_t)(m0 + lrow) * IDIM + kq;
    const float* wptr = W + (size_t)(n0 + lrow) * IDIM + kq;

    float4 av = *(const float4*)aptr;
    float4 bv = *(const float4*)wptr;

    for (int k0 = 0; k0 < IDIM; k0 += 8) {
        __syncthreads();
        As[kq + 0][lrow] = av.x; As[kq + 1][lrow] = av.y;
        As[kq + 2][lrow] = av.z; As[kq + 3][lrow] = av.w;
        Bs[kq + 0][lrow] = bv.x; Bs[kq + 1][lrow] = bv.y;
        Bs[kq + 2][lrow] = bv.z; Bs[kq + 3][lrow] = bv.w;
        __syncthreads();
        if (k0 + 8 < IDIM) {
            av = *(const float4*)(aptr + k0 + 8);
            bv = *(const float4*)(wptr + k0 + 8);
        }
#pragma unroll
        for (int k = 0; k < 8; k++) {
            float4 a0 = *(const float4*)&As[k][tm];
            float4 a1 = *(const float4*)&As[k][tm + 4];
            float4 b0 = *(const float4*)&Bs[k][tn];
            float4 b1 = *(const float4*)&Bs[k][tn + 4];
            unsigned long long am[4] = { pk2(a0.x, a0.y), pk2(a0.z, a0.w),
                                         pk2(a1.x, a1.y), pk2(a1.z, a1.w) };
            float bb[8] = { b0.x, b0.y, b0.z, b0.w, b1.x, b1.y, b1.z, b1.w };
#pragma unroll
            for (int j = 0; j < 8; j++) {
                unsigned long long b2 = pk2(bb[j], bb[j]);
                fma2(acc[0][j], am[0], b2);
                fma2(acc[1][j], am[1], b2);
                fma2(acc[2][j], am[2], b2);
                fma2(acc[3][j], am[3], b2);
            }
        }
    }

    float bias[8];
#pragma unroll
    for (int j = 0; j < 8; j++) bias[j] = bih[n0 + tn + j] + bhh[n0 + tn + j];

#pragma unroll
    for (int i = 0; i < 4; i++) {
        float r0v[8], r1v[8];
#pragma unroll
        for (int j = 0; j < 8; j++) {
            float2 p = up2(acc[i][j]);
            r0v[j] = p.x + bias[j];
            r1v[j] = p.y + bias[j];
        }
        size_t row0 = (size_t)(m0 + tm + 2 * i) * GDIM + n0 + tn;
        size_t row1 = row0 + GDIM;
        *(float4*)&g_xgates[row0]     = make_float4(r0v[0], r0v[1], r0v[2], r0v[3]);
        *(float4*)&g_xgates[row0 + 4] = make_float4(r0v[4], r0v[5], r0v[6], r0v[7]);
        *(float4*)&g_xgates[row1]     = make_float4(r1v[0], r1v[1], r1v[2], r1v[3]);
        *(float4*)&g_xgates[row1 + 4] = make_float4(r1v[4], r1v[5], r1v[6], r1v[7]);
    }
}

// ---------------- persistent LSTM recurrence ----------------------------------
// PROVEN R1 protocol (release/acquire + bar.sync), sharded counters:
//   step t wait:  threads 0..7 each ld.acquire one of 8 group counters until
//                 >= 16*t, then __syncthreads (CTA-wide visibility).
//   step t done:  lane0s store h(t+1), __syncthreads, tid0 red.release.gpu.add
//                 +1 to its group counter.
// Compute: warp w of CTA b owns h element e=b*8+w (all 4 gate rows), W_hh in
// registers, lane0 epilogue. Two h buffers + 1 barrier/step is safe: a CTA can
// only overwrite buf[t&1] (writing h(t+2)) after acquiring "all stored h(t+1)",
// and each h(t+1) store is program-ordered after that CTA's reads of h(t).
__global__ __launch_bounds__(RTHREADS, 1) void lstm_kernel(const float* __restrict__ Whh) {
    __shared__ __align__(16) float sh_h[HDIM];

    const int tid = threadIdx.x;
    const int w = tid >> 5;             // warp 0..7
    const int lane = tid & 31;
    const int b = blockIdx.x;           // 0..127
    const int e = b * 8 + w;            // owned h element
    const int grp = b >> 4;             // counter shard

    unsigned long long w01[32], w23[32];
#pragma unroll
    for (int c0 = 0; c0 < 32; c0++) {
        int col = lane + 32 * c0;
        w01[c0] = pk2(Whh[(size_t)(0 * HDIM + e) * HDIM + col],
                      Whh[(size_t)(1 * HDIM + e) * HDIM + col]);
        w23[c0] = pk2(Whh[(size_t)(2 * HDIM + e) * HDIM + col],
                      Whh[(size_t)(3 * HDIM + e) * HDIM + col]);
    }

    float c_state = 0.0f;               // lane 0's value is authoritative

    for (int t = 0; t < T_STEPS; t++) {
        // Prefetch this step's 4 xg values (independent of h; hides behind wait)
        float xg0, xg1, xg2, xg3;
        if (lane == 0) {
            const float* xr = &g_xgates[(size_t)t * GDIM + e];
            xg0 = __ldcg(xr);
            xg1 = __ldcg(xr + HDIM);
            xg2 = __ldcg(xr + 2 * HDIM);
            xg3 = __ldcg(xr + 3 * HDIM);
        }

        if (t > 0) {
            if (tid < NGRP) {
                const unsigned target = (unsigned)t * CTAS_PER_GRP;
                unsigned v;
                do {
                    asm volatile("ld.acquire.gpu.u32 %0, [%1];"
                                 : "=r"(v) : "l"(&g_ctr[tid * 32]) : "memory");
                } while (v < target);
            }
            __syncthreads();            // broadcast acquired visibility CTA-wide
            const float4* hb = (const float4*)g_h[t & 1];
            ((float4*)sh_h)[tid] = __ldcg(&hb[tid]);
        } else {
            ((float4*)sh_h)[tid] = make_float4(0.f, 0.f, 0.f, 0.f);
        }
        __syncthreads();

        unsigned long long acc01 = 0ULL, acc23 = 0ULL;
#pragma unroll
        for (int c0 = 0; c0 < 32; c0++) {
            float hv = sh_h[lane + 32 * c0];        // bank = lane: conflict-free
            unsigned long long hh = pk2(hv, hv);
            fma2(acc01, w01[c0], hh);
            fma2(acc23, w23[c0], hh);
        }
        __syncthreads();   // sh_h consumed; safe to refill next iteration

        float2 s01 = up2(acc01), s23 = up2(acc23);
#pragma unroll
        for (int off = 16; off; off >>= 1) {
            s01.x += __shfl_xor_sync(0xffffffffu, s01.x, off);
            s01.y += __shfl_xor_sync(0xffffffffu, s01.y, off);
            s23.x += __shfl_xor_sync(0xffffffffu, s23.x, off);
            s23.y += __shfl_xor_sync(0xffffffffu, s23.y, off);
        }

        if (lane == 0) {
            float i_ = fast_sigmoid(s01.x + xg0);
            float f_ = fast_sigmoid(s01.y + xg1);
            float g_ = fast_tanh(s23.x + xg2);
            float o_ = fast_sigmoid(s23.y + xg3);
            c_state = f_ * c_state + i_ * g_;
            float hn = o_ * fast_tanh(c_state);
            __stcg(&g_h[(t + 1) & 1][e], hn);
        }
        __syncthreads();   // all 8 h-stores of this CTA issued before arrival

        if (tid == 0) {
            asm volatile("red.release.gpu.add.u32 [%0], %1;"
                         :: "l"(&g_ctr[grp * 32]), "r"(1u) : "memory");
        }
    }
}

// ---------------- final: out = W_lin @ h_last + b_lin -------------------------
__global__ void final_kernel(const float* __restrict__ Wl,
                             const float* __restrict__ bl,
                             float* __restrict__ out) {
    __shared__ float partial[32];
    const int tid = threadIdx.x;     // 1024 threads
    float v = Wl[tid] * g_h[0][tid]; // h(T) lives in buffer (T_STEPS & 1) == 0
#pragma unroll
    for (int off = 16; off; off >>= 1) v += __shfl_xor_sync(0xffffffffu, v, off);
    if ((tid & 31) == 0) partial[tid >> 5] = v;
    __syncthreads();
    if (tid < 32) {
        float s = partial[tid];
#pragma unroll
        for (int off = 16; off; off >>= 1) s += __shfl_xor_sync(0xffffffffu, s, off);
        if (tid == 0) out[0] = s + bl[0];
    }
}

// ---------------- launch -------------------------------------------------------
extern "C" void kernel_launch(void* const* d_in, const int* in_sizes, int n_in,
                              void* d_out, int out_size) {
    const float* input = (const float*)d_in[0];   // [T, I]
    const float* W_ih  = (const float*)d_in[1];   // [4H, I]
    const float* W_hh  = (const float*)d_in[2];   // [4H, H]
    const float* b_ih  = (const float*)d_in[3];   // [4H]
    const float* b_hh  = (const float*)d_in[4];   // [4H]
    const float* W_lin = (const float*)d_in[5];   // [1, H]
    const float* b_lin = (const float*)d_in[6];   // [1]
    float* out = (float*)d_out;

    init_kernel<<<1, 256>>>();

    dim3 ggrid(T_STEPS / 128, GDIM / 128);        // (128, 32)
    gemm_kernel<<<ggrid, 256>>>(input, W_ih, b_ih, b_hh);

    lstm_kernel<<<NBLK, RTHREADS>>>(W_hh);

    final_kernel<<<1, 1024>>>(W_lin, b_lin, out);
}